// round 4
// baseline (speedup 1.0000x reference)
#include <cuda_runtime.h>

// NonlocalBlock: B=4, C=256, Ci=128, H=W=64 (N=4096)
// out = BN(w_out @ softmax(theta^T phi) @ g^T) + x

namespace {
constexpr int B  = 4;
constexpr int C  = 256;
constexpr int CI = 128;
constexpr int N  = 4096;
}

// ---- scratch (static device globals; no runtime allocation allowed) ----
__device__ float d_g[B * CI * N];
__device__ float d_theta[B * CI * N];
__device__ float d_phi[B * CI * N];
__device__ float d_y[B * CI * N];
__device__ float d_wy[B * C * N];
__device__ float d_psum[C * 128];
__device__ float d_psq[C * 128];
__device__ float d_bnA[C];
__device__ float d_bnB[C];

// ============================================================================
// K1: fused projection GEMM. out[oc, n] = sum_c W[oc, c] x[b, c, n] + bias
// oc in [0,384): 0-127 -> g, 128-255 -> theta, 256-383 -> phi
// grid (6, 32, 4) = (oc/64, n/128, b), 256 threads
// ============================================================================
__global__ void proj_kernel(const float* __restrict__ x,
                            const float* __restrict__ w_g, const float* __restrict__ b_g,
                            const float* __restrict__ w_t, const float* __restrict__ b_t,
                            const float* __restrict__ w_p, const float* __restrict__ b_p)
{
    __shared__ float Ws[32][65];   // [k][o], padded
    __shared__ float Xs[32][128];  // [k][n]
    const int b  = blockIdx.z;
    const int n0 = blockIdx.y * 128;
    const int o0 = blockIdx.x * 64;
    const int tid = threadIdx.x;
    const int tx = tid & 15, ty = tid >> 4;

    float acc[4][8];
#pragma unroll
    for (int i = 0; i < 4; i++)
#pragma unroll
        for (int j = 0; j < 8; j++) acc[i][j] = 0.f;

    for (int kc = 0; kc < C; kc += 32) {
        for (int idx = tid; idx < 64 * 32; idx += 256) {
            int o = idx >> 5, k = idx & 31;
            int oc = o0 + o;
            const float* w = (oc < CI) ? w_g : (oc < 2 * CI) ? w_t : w_p;
            Ws[k][o] = w[(oc & (CI - 1)) * C + kc + k];
        }
        for (int idx = tid; idx < 32 * 128; idx += 256) {
            int k = idx >> 7, n = idx & 127;
            Xs[k][n] = x[(b * C + kc + k) * N + n0 + n];
        }
        __syncthreads();
#pragma unroll 4
        for (int k = 0; k < 32; k++) {
            float a0 = Ws[k][ty * 4 + 0], a1 = Ws[k][ty * 4 + 1];
            float a2 = Ws[k][ty * 4 + 2], a3 = Ws[k][ty * 4 + 3];
            const float4 v0 = *(const float4*)&Xs[k][tx * 8];
            const float4 v1 = *(const float4*)&Xs[k][tx * 8 + 4];
            float bv[8] = {v0.x, v0.y, v0.z, v0.w, v1.x, v1.y, v1.z, v1.w};
#pragma unroll
            for (int j = 0; j < 8; j++) {
                acc[0][j] += a0 * bv[j];
                acc[1][j] += a1 * bv[j];
                acc[2][j] += a2 * bv[j];
                acc[3][j] += a3 * bv[j];
            }
        }
        __syncthreads();
    }
#pragma unroll
    for (int i = 0; i < 4; i++) {
        int oc = o0 + ty * 4 + i;
        const float* bias = (oc < CI) ? b_g : (oc < 2 * CI) ? b_t : b_p;
        float* dst = (oc < CI) ? d_g : (oc < 2 * CI) ? d_theta : d_phi;
        float bb = bias[oc & (CI - 1)];
        float* p = dst + (b * CI + (oc & (CI - 1))) * N + n0 + tx * 8;
#pragma unroll
        for (int j = 0; j < 8; j++) p[j] = acc[i][j] + bb;
    }
}

// ============================================================================
// K2: flash-style attention (no max subtraction: |logits| < ~2, exp safe).
// y[c, n] = sum_m exp(S[n,m]) g[c,m] / sum_m exp(S[n,m])
// grid (64, 4) = (n-tile of 64, b); 256 threads; dynamic smem 113 KB.
// ============================================================================
__global__ void attn_kernel()
{
    extern __shared__ float sm[];
    float* Qs = sm;                  // [ci][n]  128x64
    float* Ks = sm + 8192;           // [ci][m]  128x64
    float* Gs = sm + 16384;          // [m][c]   64x132 (padded)
    float* Ps = sm + 16384 + 8448;   // [n][m]   64x64

    const int b  = blockIdx.y;
    const int n0 = blockIdx.x * 64;
    const int tid = threadIdx.x;
    const int tx = tid & 15, ty = tid >> 4;

    for (int idx = tid; idx < 128 * 64; idx += 256) {
        int ci = idx >> 6, n = idx & 63;
        Qs[idx] = d_theta[(b * CI + ci) * N + n0 + n];
    }

    float o[4][8], l[4];
#pragma unroll
    for (int i = 0; i < 4; i++) {
        l[i] = 0.f;
#pragma unroll
        for (int j = 0; j < 8; j++) o[i][j] = 0.f;
    }

    for (int m0 = 0; m0 < N; m0 += 64) {
        for (int idx = tid; idx < 128 * 64; idx += 256) {
            int ci = idx >> 6, m = idx & 63;
            Ks[idx] = d_phi[(b * CI + ci) * N + m0 + m];
        }
        for (int idx = tid; idx < 128 * 64; idx += 256) {
            int c = idx >> 6, m = idx & 63;
            Gs[m * 132 + c] = d_g[(b * CI + c) * N + m0 + m];
        }
        __syncthreads();

        float s[4][4];
#pragma unroll
        for (int i = 0; i < 4; i++)
#pragma unroll
            for (int j = 0; j < 4; j++) s[i][j] = 0.f;

#pragma unroll 4
        for (int ci = 0; ci < 128; ci++) {
            const float4 q  = *(const float4*)&Qs[ci * 64 + ty * 4];
            const float4 k4 = *(const float4*)&Ks[ci * 64 + tx * 4];
            float qa[4] = {q.x, q.y, q.z, q.w};
            float kb[4] = {k4.x, k4.y, k4.z, k4.w};
#pragma unroll
            for (int i = 0; i < 4; i++)
#pragma unroll
                for (int j = 0; j < 4; j++) s[i][j] += qa[i] * kb[j];
        }

#pragma unroll
        for (int i = 0; i < 4; i++) {
            float rs = 0.f;
#pragma unroll
            for (int j = 0; j < 4; j++) { s[i][j] = __expf(s[i][j]); rs += s[i][j]; }
#pragma unroll
            for (int off = 1; off < 16; off <<= 1)
                rs += __shfl_xor_sync(0xffffffffu, rs, off);
            l[i] += rs;
            *(float4*)&Ps[(ty * 4 + i) * 64 + tx * 4] =
                make_float4(s[i][0], s[i][1], s[i][2], s[i][3]);
        }
        __syncthreads();

#pragma unroll 4
        for (int m = 0; m < 64; m++) {
            const float4 g0 = *(const float4*)&Gs[m * 132 + tx * 8];
            const float4 g1 = *(const float4*)&Gs[m * 132 + tx * 8 + 4];
            float gv[8] = {g0.x, g0.y, g0.z, g0.w, g1.x, g1.y, g1.z, g1.w};
#pragma unroll
            for (int i = 0; i < 4; i++) {
                float p = Ps[(ty * 4 + i) * 64 + m];
#pragma unroll
                for (int j = 0; j < 8; j++) o[i][j] += p * gv[j];
            }
        }
        __syncthreads();
    }

    // transpose through smem (reuse Qs as [c][n]) for coalesced global writes
#pragma unroll
    for (int i = 0; i < 4; i++) {
        float inv = 1.f / l[i];
#pragma unroll
        for (int j = 0; j < 8; j++)
            Qs[(tx * 8 + j) * 64 + ty * 4 + i] = o[i][j] * inv;
    }
    __syncthreads();
    for (int idx = tid; idx < 128 * 64; idx += 256) {
        int c = idx >> 6, n = idx & 63;
        d_y[(b * CI + c) * N + n0 + n] = Qs[idx];
    }
}

// ============================================================================
// K3: W_y = w_out @ y + b_out, plus deterministic BN partial sums per block.
// grid (4, 32, 4) = (oc/64, n/128, b), 256 threads.
// ============================================================================
__global__ void wy_kernel(const float* __restrict__ w_out, const float* __restrict__ b_out)
{
    __shared__ float Ws[32][65];
    __shared__ float Ys[32][128];
    const int b  = blockIdx.z;
    const int n0 = blockIdx.y * 128;
    const int o0 = blockIdx.x * 64;
    const int tid = threadIdx.x;
    const int tx = tid & 15, ty = tid >> 4;

    float acc[4][8];
#pragma unroll
    for (int i = 0; i < 4; i++)
#pragma unroll
        for (int j = 0; j < 8; j++) acc[i][j] = 0.f;

    for (int kc = 0; kc < CI; kc += 32) {
        for (int idx = tid; idx < 64 * 32; idx += 256) {
            int o = idx >> 5, k = idx & 31;
            Ws[k][o] = w_out[(o0 + o) * CI + kc + k];
        }
        for (int idx = tid; idx < 32 * 128; idx += 256) {
            int k = idx >> 7, n = idx & 127;
            Ys[k][n] = d_y[(b * CI + kc + k) * N + n0 + n];
        }
        __syncthreads();
#pragma unroll 4
        for (int k = 0; k < 32; k++) {
            float a0 = Ws[k][ty * 4 + 0], a1 = Ws[k][ty * 4 + 1];
            float a2 = Ws[k][ty * 4 + 2], a3 = Ws[k][ty * 4 + 3];
            const float4 v0 = *(const float4*)&Ys[k][tx * 8];
            const float4 v1 = *(const float4*)&Ys[k][tx * 8 + 4];
            float bv[8] = {v0.x, v0.y, v0.z, v0.w, v1.x, v1.y, v1.z, v1.w};
#pragma unroll
            for (int j = 0; j < 8; j++) {
                acc[0][j] += a0 * bv[j];
                acc[1][j] += a1 * bv[j];
                acc[2][j] += a2 * bv[j];
                acc[3][j] += a3 * bv[j];
            }
        }
        __syncthreads();
    }

#pragma unroll
    for (int i = 0; i < 4; i++) {
        int oc = o0 + ty * 4 + i;
        float bb = b_out[oc];
        float s = 0.f, q = 0.f;
        float* p = d_wy + (b * C + oc) * N + n0 + tx * 8;
#pragma unroll
        for (int j = 0; j < 8; j++) {
            float v = acc[i][j] + bb;
            p[j] = v;
            s += v;
            q += v * v;
        }
#pragma unroll
        for (int off = 1; off < 16; off <<= 1) {
            s += __shfl_xor_sync(0xffffffffu, s, off);
            q += __shfl_xor_sync(0xffffffffu, q, off);
        }
        if (tx == 0) {
            int part = b * 32 + blockIdx.y;       // [0,128)
            d_psum[oc * 128 + part] = s;          // written exactly once -> deterministic
            d_psq[oc * 128 + part]  = q;
        }
    }
}

// ============================================================================
// K4: reduce BN partials -> per-channel scale/shift
// ============================================================================
__global__ void bnstat_kernel(const float* __restrict__ gamma, const float* __restrict__ beta)
{
    int c = threadIdx.x;
    float s = 0.f, q = 0.f;
    for (int p = 0; p < 128; p++) {
        s += d_psum[c * 128 + p];
        q += d_psq[c * 128 + p];
    }
    const float invn = 1.f / 16384.f;  // B*N
    float mean = s * invn;
    float var  = q * invn - mean * mean;
    float sc   = gamma[c] * rsqrtf(var + 1e-5f);
    d_bnA[c] = sc;
    d_bnB[c] = beta[c] - mean * sc;
}

// ============================================================================
// K5: out = W_y * scale[c] + shift[c] + x  (vectorized)
// ============================================================================
__global__ void bnadd_kernel(const float* __restrict__ x, float* __restrict__ out)
{
    int idx4 = blockIdx.x * blockDim.x + threadIdx.x;
    if (idx4 >= B * C * N / 4) return;
    int c = (idx4 >> 10) & (C - 1);  // N/4 = 1024 float4 per channel
    float sc = d_bnA[c], bb = d_bnB[c];
    float4 w  = ((const float4*)d_wy)[idx4];
    float4 xv = ((const float4*)x)[idx4];
    float4 r;
    r.x = w.x * sc + bb + xv.x;
    r.y = w.y * sc + bb + xv.y;
    r.z = w.z * sc + bb + xv.z;
    r.w = w.w * sc + bb + xv.w;
    ((float4*)out)[idx4] = r;
}

// ============================================================================
extern "C" void kernel_launch(void* const* d_in, const int* in_sizes, int n_in,
                              void* d_out, int out_size)
{
    const float* x     = (const float*)d_in[0];
    const float* w_g   = (const float*)d_in[1];
    const float* b_g   = (const float*)d_in[2];
    const float* w_t   = (const float*)d_in[3];
    const float* b_t   = (const float*)d_in[4];
    const float* w_p   = (const float*)d_in[5];
    const float* b_p   = (const float*)d_in[6];
    const float* w_o   = (const float*)d_in[7];
    const float* b_o   = (const float*)d_in[8];
    const float* gamma = (const float*)d_in[9];
    const float* beta  = (const float*)d_in[10];
    float* out = (float*)d_out;

    cudaFuncSetAttribute(attn_kernel, cudaFuncAttributeMaxDynamicSharedMemorySize, 115712);

    proj_kernel<<<dim3(6, 32, 4), 256>>>(x, w_g, b_g, w_t, b_t, w_p, b_p);
    attn_kernel<<<dim3(64, 4), 256, 115712>>>();
    wy_kernel<<<dim3(4, 32, 4), 256>>>(w_o, b_o);
    bnstat_kernel<<<1, 256>>>(gamma, beta);
    bnadd_kernel<<<4096, 256>>>(x, out);
}

// round 7
// speedup vs baseline: 2.5121x; 2.5121x over previous
#include <cuda_runtime.h>
#include <cuda_bf16.h>
#include <cstdint>

// NonlocalBlock: B=4, C=256, Ci=128, H=W=64 (N=4096)
// out = BN(w_out @ softmax(theta^T phi) @ g^T) + x
// Attention via warp-level mma.sync (HMMA bf16) with bf16x2 hi/lo compensation.
// (tcgen05 is NOT available: harness compiles via compute_103 -> ptxas rejects it.)

namespace {
constexpr int B  = 4;
constexpr int C  = 256;
constexpr int CI = 128;
constexpr int N  = 4096;
}

// ---- scratch (static device globals; no runtime allocation allowed) ----
__device__ float d_y[B * CI * N];
__device__ float d_wy[B * C * N];
__device__ float d_psum[C * 128];
__device__ float d_psq[C * 128];
__device__ float d_bnA[C];
__device__ float d_bnB[C];
// bf16 hi/lo operands for tensor-core attention
__device__ alignas(16) __nv_bfloat16 d_thT_hi[B * N * CI];  // [b][n][ci]
__device__ alignas(16) __nv_bfloat16 d_thT_lo[B * N * CI];
__device__ alignas(16) __nv_bfloat16 d_phT_hi[B * N * CI];  // [b][m][ci]
__device__ alignas(16) __nv_bfloat16 d_phT_lo[B * N * CI];
__device__ alignas(16) __nv_bfloat16 d_g_hi[B * CI * N];    // [b][c][m]
__device__ alignas(16) __nv_bfloat16 d_g_lo[B * CI * N];

// ============================================================================
// helpers
// ============================================================================
__device__ __forceinline__ uint32_t smem_u32(const void* p) {
    uint32_t a;
    asm("{ .reg .u64 t; cvta.to.shared.u64 t, %1; cvt.u32.u64 %0, t; }" : "=r"(a) : "l"(p));
    return a;
}
__device__ __forceinline__ uint16_t f2bf(float v) {
    return __bfloat16_as_ushort(__float2bfloat16(v));
}
__device__ __forceinline__ float bf2f(uint16_t u) {
    return __bfloat162float(__ushort_as_bfloat16(u));
}
__device__ __forceinline__ uint32_t pack2(uint16_t lo, uint16_t hi) {
    return (uint32_t)lo | ((uint32_t)hi << 16);
}
// D(16x8,f32) += A(16x16,bf16 row) * B(16x8,bf16 col)
__device__ __forceinline__ void mma_bf16(float* c,
                                         uint32_t a0, uint32_t a1, uint32_t a2, uint32_t a3,
                                         uint32_t b0, uint32_t b1) {
    asm volatile(
        "mma.sync.aligned.m16n8k16.row.col.f32.bf16.bf16.f32 "
        "{%0,%1,%2,%3}, {%4,%5,%6,%7}, {%8,%9}, {%0,%1,%2,%3};"
        : "+f"(c[0]), "+f"(c[1]), "+f"(c[2]), "+f"(c[3])
        : "r"(a0), "r"(a1), "r"(a2), "r"(a3), "r"(b0), "r"(b1));
}
__device__ __forceinline__ void ldsm_x4(uint32_t addr, uint32_t& r0, uint32_t& r1,
                                        uint32_t& r2, uint32_t& r3) {
    asm volatile("ldmatrix.sync.aligned.m8n8.x4.shared.b16 {%0,%1,%2,%3}, [%4];"
                 : "=r"(r0), "=r"(r1), "=r"(r2), "=r"(r3) : "r"(addr));
}

// ============================================================================
// K1: fused projection GEMM. Emits bf16 hi/lo operands:
//   thetaT/phiT [b][n][ci] (transposed for MMA A/B), g [b][c][m].
// grid (6, 32, 4) = (oc/64, n/128, b), 256 threads
// ============================================================================
__global__ void proj_kernel(const float* __restrict__ x,
                            const float* __restrict__ w_g, const float* __restrict__ b_g,
                            const float* __restrict__ w_t, const float* __restrict__ b_t,
                            const float* __restrict__ w_p, const float* __restrict__ b_p)
{
    __shared__ float Ws[32][65];
    __shared__ float Xs[32][128];
    const int b  = blockIdx.z;
    const int n0 = blockIdx.y * 128;
    const int o0 = blockIdx.x * 64;
    const int tid = threadIdx.x;
    const int tx = tid & 15, ty = tid >> 4;

    float acc[4][8];
#pragma unroll
    for (int i = 0; i < 4; i++)
#pragma unroll
        for (int j = 0; j < 8; j++) acc[i][j] = 0.f;

    for (int kc = 0; kc < C; kc += 32) {
        for (int idx = tid; idx < 64 * 32; idx += 256) {
            int o = idx >> 5, k = idx & 31;
            int oc = o0 + o;
            const float* w = (oc < CI) ? w_g : (oc < 2 * CI) ? w_t : w_p;
            Ws[k][o] = w[(oc & (CI - 1)) * C + kc + k];
        }
        for (int idx = tid; idx < 32 * 128; idx += 256) {
            int k = idx >> 7, n = idx & 127;
            Xs[k][n] = x[(b * C + kc + k) * N + n0 + n];
        }
        __syncthreads();
#pragma unroll 4
        for (int k = 0; k < 32; k++) {
            float a0 = Ws[k][ty * 4 + 0], a1 = Ws[k][ty * 4 + 1];
            float a2 = Ws[k][ty * 4 + 2], a3 = Ws[k][ty * 4 + 3];
            const float4 v0 = *(const float4*)&Xs[k][tx * 8];
            const float4 v1 = *(const float4*)&Xs[k][tx * 8 + 4];
            float bv[8] = {v0.x, v0.y, v0.z, v0.w, v1.x, v1.y, v1.z, v1.w};
#pragma unroll
            for (int j = 0; j < 8; j++) {
                acc[0][j] += a0 * bv[j];
                acc[1][j] += a1 * bv[j];
                acc[2][j] += a2 * bv[j];
                acc[3][j] += a3 * bv[j];
            }
        }
        __syncthreads();
    }

    const int oc0 = o0 + ty * 4;
    float v[4][8];
#pragma unroll
    for (int i = 0; i < 4; i++) {
        int ocl = (oc0 + i) & (CI - 1);
        float bb = (o0 < CI) ? b_g[ocl] : (o0 < 2 * CI) ? b_t[ocl] : b_p[ocl];
#pragma unroll
        for (int j = 0; j < 8; j++) v[i][j] = acc[i][j] + bb;
    }

    if (o0 < CI) {
        // g: [b][c][m] rows, 8 consecutive m per thread
#pragma unroll
        for (int i = 0; i < 4; i++) {
            uint32_t ph[4], pl[4];
#pragma unroll
            for (int jj = 0; jj < 4; jj++) {
                uint16_t h0 = f2bf(v[i][2 * jj]), h1 = f2bf(v[i][2 * jj + 1]);
                uint16_t l0 = f2bf(v[i][2 * jj] - bf2f(h0));
                uint16_t l1 = f2bf(v[i][2 * jj + 1] - bf2f(h1));
                ph[jj] = pack2(h0, h1);
                pl[jj] = pack2(l0, l1);
            }
            size_t base = (size_t)(b * CI + oc0 + i) * N + n0 + tx * 8;
            *(uint4*)(d_g_hi + base) = make_uint4(ph[0], ph[1], ph[2], ph[3]);
            *(uint4*)(d_g_lo + base) = make_uint4(pl[0], pl[1], pl[2], pl[3]);
        }
    } else {
        __nv_bfloat16* dh = (o0 < 2 * CI) ? d_thT_hi : d_phT_hi;
        __nv_bfloat16* dl = (o0 < 2 * CI) ? d_thT_lo : d_phT_lo;
        int ocl0 = oc0 & (CI - 1);
#pragma unroll
        for (int j = 0; j < 8; j++) {
            int n = n0 + tx * 8 + j;
            uint32_t ph[2], pl[2];
#pragma unroll
            for (int ii = 0; ii < 2; ii++) {
                uint16_t h0 = f2bf(v[2 * ii][j]), h1 = f2bf(v[2 * ii + 1][j]);
                uint16_t l0 = f2bf(v[2 * ii][j] - bf2f(h0));
                uint16_t l1 = f2bf(v[2 * ii + 1][j] - bf2f(h1));
                ph[ii] = pack2(h0, h1);
                pl[ii] = pack2(l0, l1);
            }
            size_t base = (size_t)(b * N + n) * CI + ocl0;
            *(uint2*)(dh + base) = make_uint2(ph[0], ph[1]);
            *(uint2*)(dl + base) = make_uint2(pl[0], pl[1]);
        }
    }
}

// ============================================================================
// K2: HMMA flash attention.
// Block = 128 query rows; 8 warps x 16 rows. Loop m-tiles of 64.
// S = th_hi*ph_hi + th_hi*ph_lo + th_lo*ph_hi  (fp32 accum)
// P = exp(S), split hi/lo in REGISTERS (accum layout == A-frag layout),
// Y += P_hi*G_hi + P_hi*G_lo + P_lo*G_hi.
// grid (32, 4), 256 threads, dyn smem 71680 B.
// ============================================================================
#define PHI_PITCH 272   // bytes per 128-bf16 row (padded: 68 words, 4 mod 32)
#define G_PITCH   144   // bytes per 64-bf16 row  (padded: 36 words, 4 mod 32)
#define OFF_PHI_HI 0u
#define OFF_PHI_LO 17408u
#define OFF_G_HI   34816u
#define OFF_G_LO   53248u
#define ATTN_SMEM  71680

__global__ void __launch_bounds__(256, 1) attn_kernel()
{
    extern __shared__ char smc[];
    const uint32_t sb = smem_u32(smc);
    const int b   = blockIdx.y;
    const int n0  = blockIdx.x * 128;
    const int tid = threadIdx.x;
    const int wid = tid >> 5, lane = tid & 31;
    const int gid = lane >> 2, tig = lane & 3;   // row group / thread-in-group
    const int sel = lane >> 3, lr = lane & 7;    // ldmatrix matrix select / row

    // ---- load theta A-fragments once (16 rows per warp), hi+lo ----
    uint32_t a_hi[8][4], a_lo[8][4];
    {
        const size_t rowbase = (size_t)(b * N + n0 + 16 * wid);
        const __nv_bfloat16* th = d_thT_hi + rowbase * CI;
        const __nv_bfloat16* tl = d_thT_lo + rowbase * CI;
        const int r0 = gid, r1 = gid + 8, c0 = 2 * tig;
#pragma unroll
        for (int k = 0; k < 8; k++) {
            a_hi[k][0] = *(const uint32_t*)(th + (size_t)r0 * CI + 16 * k + c0);
            a_hi[k][1] = *(const uint32_t*)(th + (size_t)r1 * CI + 16 * k + c0);
            a_hi[k][2] = *(const uint32_t*)(th + (size_t)r0 * CI + 16 * k + c0 + 8);
            a_hi[k][3] = *(const uint32_t*)(th + (size_t)r1 * CI + 16 * k + c0 + 8);
            a_lo[k][0] = *(const uint32_t*)(tl + (size_t)r0 * CI + 16 * k + c0);
            a_lo[k][1] = *(const uint32_t*)(tl + (size_t)r1 * CI + 16 * k + c0);
            a_lo[k][2] = *(const uint32_t*)(tl + (size_t)r0 * CI + 16 * k + c0 + 8);
            a_lo[k][3] = *(const uint32_t*)(tl + (size_t)r1 * CI + 16 * k + c0 + 8);
        }
    }

    float y[16][4];
#pragma unroll
    for (int t = 0; t < 16; t++)
#pragma unroll
        for (int e = 0; e < 4; e++) y[t][e] = 0.f;
    float l_lo = 0.f, l_hi = 0.f;

    for (int it = 0; it < 64; ++it) {
        const int m0 = it * 64;
        __syncthreads();  // previous iter's tile reads done

        // ---- stage phi (64 x 128, hi+lo) and g (128 x 64, hi+lo) ----
        {
            const __nv_bfloat16* ph = d_phT_hi + (size_t)(b * N + m0) * CI;
            const __nv_bfloat16* pl = d_phT_lo + (size_t)(b * N + m0) * CI;
            for (int idx = tid; idx < 64 * 16; idx += 256) {
                int r = idx >> 4, ch = idx & 15;
                uint32_t o = (uint32_t)r * PHI_PITCH + (uint32_t)ch * 16;
                *(uint4*)(smc + OFF_PHI_HI + o) = *(const uint4*)(ph + (size_t)r * CI + ch * 8);
                *(uint4*)(smc + OFF_PHI_LO + o) = *(const uint4*)(pl + (size_t)r * CI + ch * 8);
            }
            const __nv_bfloat16* gh = d_g_hi + (size_t)b * CI * N + m0;
            const __nv_bfloat16* gl = d_g_lo + (size_t)b * CI * N + m0;
            for (int idx = tid; idx < 128 * 8; idx += 256) {
                int r = idx >> 3, ch = idx & 7;
                uint32_t o = (uint32_t)r * G_PITCH + (uint32_t)ch * 16;
                *(uint4*)(smc + OFF_G_HI + o) = *(const uint4*)(gh + (size_t)r * N + ch * 8);
                *(uint4*)(smc + OFF_G_LO + o) = *(const uint4*)(gl + (size_t)r * N + ch * 8);
            }
        }
        __syncthreads();

        // ---- QK: S[16 x 64] ----
        float s[8][4];
#pragma unroll
        for (int j = 0; j < 8; j++)
#pragma unroll
            for (int e = 0; e < 4; e++) s[j][e] = 0.f;

#pragma unroll
        for (int j = 0; j < 8; j++) {
#pragma unroll
            for (int k = 0; k < 8; k++) {
                uint32_t addr = sb + ((sel >= 2) ? OFF_PHI_LO : OFF_PHI_HI)
                              + (uint32_t)(8 * j + lr) * PHI_PITCH
                              + (uint32_t)k * 32 + (uint32_t)(sel & 1) * 16;
                uint32_t bh0, bh1, bl0, bl1;
                ldsm_x4(addr, bh0, bh1, bl0, bl1);
                mma_bf16(s[j], a_hi[k][0], a_hi[k][1], a_hi[k][2], a_hi[k][3], bh0, bh1);
                mma_bf16(s[j], a_hi[k][0], a_hi[k][1], a_hi[k][2], a_hi[k][3], bl0, bl1);
                mma_bf16(s[j], a_lo[k][0], a_lo[k][1], a_lo[k][2], a_lo[k][3], bh0, bh1);
            }
        }

        // ---- exp + rowsum + pack P fragments (registers only) ----
        float rs0 = 0.f, rs1 = 0.f;
        uint32_t pa_hi[4][4], pa_lo[4][4];
#pragma unroll
        for (int j = 0; j < 8; j++) {
#pragma unroll
            for (int e = 0; e < 4; e++) s[j][e] = __expf(s[j][e]);
            rs0 += s[j][0] + s[j][1];
            rs1 += s[j][2] + s[j][3];
        }
#pragma unroll
        for (int k = 0; k < 4; k++) {
            const int j0 = 2 * k, j1 = 2 * k + 1;
            uint16_t h00 = f2bf(s[j0][0]), h01 = f2bf(s[j0][1]);
            uint16_t h02 = f2bf(s[j0][2]), h03 = f2bf(s[j0][3]);
            uint16_t h10 = f2bf(s[j1][0]), h11 = f2bf(s[j1][1]);
            uint16_t h12 = f2bf(s[j1][2]), h13 = f2bf(s[j1][3]);
            pa_hi[k][0] = pack2(h00, h01);
            pa_hi[k][1] = pack2(h02, h03);
            pa_hi[k][2] = pack2(h10, h11);
            pa_hi[k][3] = pack2(h12, h13);
            pa_lo[k][0] = pack2(f2bf(s[j0][0] - bf2f(h00)), f2bf(s[j0][1] - bf2f(h01)));
            pa_lo[k][1] = pack2(f2bf(s[j0][2] - bf2f(h02)), f2bf(s[j0][3] - bf2f(h03)));
            pa_lo[k][2] = pack2(f2bf(s[j1][0] - bf2f(h10)), f2bf(s[j1][1] - bf2f(h11)));
            pa_lo[k][3] = pack2(f2bf(s[j1][2] - bf2f(h12)), f2bf(s[j1][3] - bf2f(h13)));
        }
        rs0 += __shfl_xor_sync(0xffffffffu, rs0, 1);
        rs0 += __shfl_xor_sync(0xffffffffu, rs0, 2);
        rs1 += __shfl_xor_sync(0xffffffffu, rs1, 1);
        rs1 += __shfl_xor_sync(0xffffffffu, rs1, 2);
        l_lo += rs0;
        l_hi += rs1;

        // ---- PV: Y[16 x 128] += P * G^T ----
#pragma unroll
        for (int ct = 0; ct < 16; ct++) {
#pragma unroll
            for (int k = 0; k < 4; k++) {
                uint32_t addr = sb + ((sel >= 2) ? OFF_G_LO : OFF_G_HI)
                              + (uint32_t)(8 * ct + lr) * G_PITCH
                              + (uint32_t)k * 32 + (uint32_t)(sel & 1) * 16;
                uint32_t gh0, gh1, gl0, gl1;
                ldsm_x4(addr, gh0, gh1, gl0, gl1);
                mma_bf16(y[ct], pa_hi[k][0], pa_hi[k][1], pa_hi[k][2], pa_hi[k][3], gh0, gh1);
                mma_bf16(y[ct], pa_hi[k][0], pa_hi[k][1], pa_hi[k][2], pa_hi[k][3], gl0, gl1);
                mma_bf16(y[ct], pa_lo[k][0], pa_lo[k][1], pa_lo[k][2], pa_lo[k][3], gh0, gh1);
            }
        }
    }

    // ---- normalize + transpose via smem -> coalesced d_y [b][c][n] ----
    __syncthreads();  // done with tiles; reuse smem for staging
    float* ysm = (float*)smc;  // [128 c][pitch 132] floats
    const float inv0 = 1.f / l_lo, inv1 = 1.f / l_hi;
    const int nl0 = 16 * wid + gid, nl1 = nl0 + 8;
#pragma unroll
    for (int ct = 0; ct < 16; ct++) {
        int c = 8 * ct + 2 * tig;
        ysm[(c + 0) * 132 + nl0] = y[ct][0] * inv0;
        ysm[(c + 1) * 132 + nl0] = y[ct][1] * inv0;
        ysm[(c + 0) * 132 + nl1] = y[ct][2] * inv1;
        ysm[(c + 1) * 132 + nl1] = y[ct][3] * inv1;
    }
    __syncthreads();
    for (int idx = tid; idx < 128 * 128; idx += 256) {
        int c = idx >> 7, n = idx & 127;
        d_y[(size_t)(b * CI + c) * N + n0 + n] = ysm[c * 132 + n];
    }
}

// ============================================================================
// K3: W_y = w_out @ y + b_out, plus deterministic BN partial sums per block.
// grid (4, 32, 4) = (oc/64, n/128, b), 256 threads.
// ============================================================================
__global__ void wy_kernel(const float* __restrict__ w_out, const float* __restrict__ b_out)
{
    __shared__ float Ws[32][65];
    __shared__ float Ys[32][128];
    const int b  = blockIdx.z;
    const int n0 = blockIdx.y * 128;
    const int o0 = blockIdx.x * 64;
    const int tid = threadIdx.x;
    const int tx = tid & 15, ty = tid >> 4;

    float acc[4][8];
#pragma unroll
    for (int i = 0; i < 4; i++)
#pragma unroll
        for (int j = 0; j < 8; j++) acc[i][j] = 0.f;

    for (int kc = 0; kc < CI; kc += 32) {
        for (int idx = tid; idx < 64 * 32; idx += 256) {
            int o = idx >> 5, k = idx & 31;
            Ws[k][o] = w_out[(o0 + o) * CI + kc + k];
        }
        for (int idx = tid; idx < 32 * 128; idx += 256) {
            int k = idx >> 7, n = idx & 127;
            Ys[k][n] = d_y[(size_t)(b * CI + kc + k) * N + n0 + n];
        }
        __syncthreads();
#pragma unroll 4
        for (int k = 0; k < 32; k++) {
            float a0 = Ws[k][ty * 4 + 0], a1 = Ws[k][ty * 4 + 1];
            float a2 = Ws[k][ty * 4 + 2], a3 = Ws[k][ty * 4 + 3];
            const float4 v0 = *(const float4*)&Ys[k][tx * 8];
            const float4 v1 = *(const float4*)&Ys[k][tx * 8 + 4];
            float bv[8] = {v0.x, v0.y, v0.z, v0.w, v1.x, v1.y, v1.z, v1.w};
#pragma unroll
            for (int j = 0; j < 8; j++) {
                acc[0][j] += a0 * bv[j];
                acc[1][j] += a1 * bv[j];
                acc[2][j] += a2 * bv[j];
                acc[3][j] += a3 * bv[j];
            }
        }
        __syncthreads();
    }

#pragma unroll
    for (int i = 0; i < 4; i++) {
        int oc = o0 + ty * 4 + i;
        float bb = b_out[oc];
        float s = 0.f, q = 0.f;
        float* p = d_wy + (size_t)(b * C + oc) * N + n0 + tx * 8;
#pragma unroll
        for (int j = 0; j < 8; j++) {
            float vv = acc[i][j] + bb;
            p[j] = vv;
            s += vv;
            q += vv * vv;
        }
#pragma unroll
        for (int off = 1; off < 16; off <<= 1) {
            s += __shfl_xor_sync(0xffffffffu, s, off);
            q += __shfl_xor_sync(0xffffffffu, q, off);
        }
        if (tx == 0) {
            int part = b * 32 + blockIdx.y;
            d_psum[oc * 128 + part] = s;
            d_psq[oc * 128 + part]  = q;
        }
    }
}

// ============================================================================
// K4: reduce BN partials -> per-channel scale/shift. grid C=256, 32 threads.
// ============================================================================
__global__ void bnstat_kernel(const float* __restrict__ gamma, const float* __restrict__ beta)
{
    int c = blockIdx.x, t = threadIdx.x;
    float s = 0.f, q = 0.f;
#pragma unroll
    for (int p = t; p < 128; p += 32) {
        s += d_psum[c * 128 + p];
        q += d_psq[c * 128 + p];
    }
#pragma unroll
    for (int off = 1; off < 32; off <<= 1) {
        s += __shfl_xor_sync(0xffffffffu, s, off);
        q += __shfl_xor_sync(0xffffffffu, q, off);
    }
    if (t == 0) {
        const float invn = 1.f / 16384.f;  // B*N
        float mean = s * invn;
        float var  = q * invn - mean * mean;
        float sc   = gamma[c] * rsqrtf(var + 1e-5f);
        d_bnA[c] = sc;
        d_bnB[c] = beta[c] - mean * sc;
    }
}

// ============================================================================
// K5: out = W_y * scale[c] + shift[c] + x  (vectorized)
// ============================================================================
__global__ void bnadd_kernel(const float* __restrict__ x, float* __restrict__ out)
{
    int idx4 = blockIdx.x * blockDim.x + threadIdx.x;
    if (idx4 >= B * C * N / 4) return;
    int c = (idx4 >> 10) & (C - 1);
    float sc = d_bnA[c], bb = d_bnB[c];
    float4 w  = ((const float4*)d_wy)[idx4];
    float4 xv = ((const float4*)x)[idx4];
    float4 r;
    r.x = w.x * sc + bb + xv.x;
    r.y = w.y * sc + bb + xv.y;
    r.z = w.z * sc + bb + xv.z;
    r.w = w.w * sc + bb + xv.w;
    ((float4*)out)[idx4] = r;
}

// ============================================================================
extern "C" void kernel_launch(void* const* d_in, const int* in_sizes, int n_in,
                              void* d_out, int out_size)
{
    const float* x     = (const float*)d_in[0];
    const float* w_g   = (const float*)d_in[1];
    const float* b_g   = (const float*)d_in[2];
    const float* w_t   = (const float*)d_in[3];
    const float* b_t   = (const float*)d_in[4];
    const float* w_p   = (const float*)d_in[5];
    const float* b_p   = (const float*)d_in[6];
    const float* w_o   = (const float*)d_in[7];
    const float* b_o   = (const float*)d_in[8];
    const float* gamma = (const float*)d_in[9];
    const float* beta  = (const float*)d_in[10];
    float* out = (float*)d_out;

    cudaFuncSetAttribute(attn_kernel, cudaFuncAttributeMaxDynamicSharedMemorySize, ATTN_SMEM);

    proj_kernel<<<dim3(6, 32, 4), 256>>>(x, w_g, b_g, w_t, b_t, w_p, b_p);
    attn_kernel<<<dim3(32, 4), 256, ATTN_SMEM>>>();
    wy_kernel<<<dim3(4, 32, 4), 256>>>(w_o, b_o);
    bnstat_kernel<<<256, 32>>>(gamma, beta);
    bnadd_kernel<<<4096, 256>>>(x, out);
}

// round 8
// speedup vs baseline: 3.8547x; 1.5344x over previous
#include <cuda_runtime.h>
#include <cuda_bf16.h>
#include <cstdint>

// NonlocalBlock: B=4, C=256, Ci=128, H=W=64 (N=4096)
// out = BN(w_out @ softmax(theta^T phi) @ g^T) + x
// HMMA (mma.sync bf16) everywhere heavy, bf16x2 hi/lo compensation (3 chains).
// cp.async 2-stage pipelines in proj + attn.

namespace {
constexpr int B  = 4;
constexpr int C  = 256;
constexpr int CI = 128;
constexpr int N  = 4096;
}

// ---- scratch (static device globals; no runtime allocation allowed) ----
__device__ float d_y[B * CI * N];
__device__ float d_wy[B * C * N];
__device__ float d_psum[C * 128];
__device__ float d_psq[C * 128];
__device__ float d_bnA[C];
__device__ float d_bnB[C];
// bf16 hi/lo operands
__device__ alignas(16) __nv_bfloat16 d_thT_hi[B * N * CI];  // [b][n][ci]
__device__ alignas(16) __nv_bfloat16 d_thT_lo[B * N * CI];
__device__ alignas(16) __nv_bfloat16 d_phT_hi[B * N * CI];  // [b][m][ci]
__device__ alignas(16) __nv_bfloat16 d_phT_lo[B * N * CI];
__device__ alignas(16) __nv_bfloat16 d_g_hi[B * CI * N];    // [b][c][m]
__device__ alignas(16) __nv_bfloat16 d_g_lo[B * CI * N];
// split inputs for HMMA proj
__device__ alignas(16) __nv_bfloat16 d_W_hi[384 * 256];     // rows: 0-127 g,128-255 th,256-383 phi
__device__ alignas(16) __nv_bfloat16 d_W_lo[384 * 256];
__device__ alignas(16) __nv_bfloat16 d_x_hi[B * C * N];     // [b][c][n]
__device__ alignas(16) __nv_bfloat16 d_x_lo[B * C * N];

// ============================================================================
// helpers
// ============================================================================
__device__ __forceinline__ uint32_t smem_u32(const void* p) {
    uint32_t a;
    asm("{ .reg .u64 t; cvta.to.shared.u64 t, %1; cvt.u32.u64 %0, t; }" : "=r"(a) : "l"(p));
    return a;
}
__device__ __forceinline__ uint16_t f2bf(float v) {
    return __bfloat16_as_ushort(__float2bfloat16(v));
}
__device__ __forceinline__ float bf2f(uint16_t u) {
    return __bfloat162float(__ushort_as_bfloat16(u));
}
__device__ __forceinline__ uint32_t pack2(uint16_t lo, uint16_t hi) {
    return (uint32_t)lo | ((uint32_t)hi << 16);
}
__device__ __forceinline__ void mma_bf16(float* c,
                                         uint32_t a0, uint32_t a1, uint32_t a2, uint32_t a3,
                                         uint32_t b0, uint32_t b1) {
    asm volatile(
        "mma.sync.aligned.m16n8k16.row.col.f32.bf16.bf16.f32 "
        "{%0,%1,%2,%3}, {%4,%5,%6,%7}, {%8,%9}, {%0,%1,%2,%3};"
        : "+f"(c[0]), "+f"(c[1]), "+f"(c[2]), "+f"(c[3])
        : "r"(a0), "r"(a1), "r"(a2), "r"(a3), "r"(b0), "r"(b1));
}
__device__ __forceinline__ void ldsm_x4(uint32_t addr, uint32_t& r0, uint32_t& r1,
                                        uint32_t& r2, uint32_t& r3) {
    asm volatile("ldmatrix.sync.aligned.m8n8.x4.shared.b16 {%0,%1,%2,%3}, [%4];"
                 : "=r"(r0), "=r"(r1), "=r"(r2), "=r"(r3) : "r"(addr));
}
__device__ __forceinline__ void ldsm_x4_t(uint32_t addr, uint32_t& r0, uint32_t& r1,
                                          uint32_t& r2, uint32_t& r3) {
    asm volatile("ldmatrix.sync.aligned.m8n8.x4.trans.shared.b16 {%0,%1,%2,%3}, [%4];"
                 : "=r"(r0), "=r"(r1), "=r"(r2), "=r"(r3) : "r"(addr));
}
__device__ __forceinline__ void cp16(uint32_t saddr, const void* gaddr) {
    asm volatile("cp.async.cg.shared.global [%0], [%1], 16;" :: "r"(saddr), "l"(gaddr));
}
#define CP_COMMIT() asm volatile("cp.async.commit_group;" ::: "memory")
#define CP_WAIT(n)  asm volatile("cp.async.wait_group %0;" :: "n"(n) : "memory")

// ============================================================================
// K0a: split weights (w_g|w_t|w_p rows) -> d_W_hi/lo. grid 384 x 256.
// ============================================================================
__global__ void splitw_kernel(const float* __restrict__ w_g,
                              const float* __restrict__ w_t,
                              const float* __restrict__ w_p)
{
    int row = blockIdx.x, t = threadIdx.x;
    const float* src = (row < 128) ? w_g + (size_t)row * 256
                     : (row < 256) ? w_t + (size_t)(row - 128) * 256
                                   : w_p + (size_t)(row - 256) * 256;
    float v = src[t];
    uint16_t h = f2bf(v);
    d_W_hi[(size_t)row * 256 + t] = __ushort_as_bfloat16(h);
    d_W_lo[(size_t)row * 256 + t] = __ushort_as_bfloat16(f2bf(v - bf2f(h)));
}

// ============================================================================
// K0b: split x -> d_x_hi/lo. grid 4096 x 256, float4 per thread.
// ============================================================================
__global__ void splitx_kernel(const float* __restrict__ x)
{
    int idx4 = blockIdx.x * blockDim.x + threadIdx.x;  // < B*C*N/4
    float4 v = ((const float4*)x)[idx4];
    uint16_t h0 = f2bf(v.x), h1 = f2bf(v.y), h2 = f2bf(v.z), h3 = f2bf(v.w);
    *(uint2*)(d_x_hi + (size_t)idx4 * 4) = make_uint2(pack2(h0, h1), pack2(h2, h3));
    *(uint2*)(d_x_lo + (size_t)idx4 * 4) =
        make_uint2(pack2(f2bf(v.x - bf2f(h0)), f2bf(v.y - bf2f(h1))),
                   pack2(f2bf(v.z - bf2f(h2)), f2bf(v.w - bf2f(h3))));
}

// ============================================================================
// K1: HMMA projection GEMM. out[128 oc][128 n] per block, K=256 in 8 chunks of 32,
// cp.async 2-stage. 3 compensation chains. grid (3 mt, 32 nt, 4 b), 256 thr.
// mt: 0 -> g [b][oc][n]; 1 -> thT [b][n][oc]; 2 -> phT [b][n][oc]  (hi+lo each)
// ============================================================================
#define PJ_WHI   0u
#define PJ_WLO   10240u     // 128 rows x 80B
#define PJ_XHI   20480u
#define PJ_XLO   29184u     // 32 rows x 272B
#define PJ_STAGE 37888u
#define PROJ_SMEM 75776

__global__ void __launch_bounds__(256, 2) proj_kernel(const float* __restrict__ b_g,
                                                      const float* __restrict__ b_t,
                                                      const float* __restrict__ b_p)
{
    extern __shared__ char smc[];
    const uint32_t sb = smem_u32(smc);
    const int mt = blockIdx.x;
    const int n0 = blockIdx.y * 128;
    const int b  = blockIdx.z;
    const int tid = threadIdx.x, wid = tid >> 5, lane = tid & 31;
    const int gid = lane >> 2, tig = lane & 3;
    const int obase = mt * 128;

    float acc[16][4];
#pragma unroll
    for (int nf = 0; nf < 16; nf++)
#pragma unroll
        for (int e = 0; e < 4; e++) acc[nf][e] = 0.f;

    auto load_chunk = [&](int st, int kc) {
        uint32_t base = sb + (uint32_t)st * PJ_STAGE;
        for (int idx = tid; idx < 512; idx += 256) {
            int r = idx >> 2, sg = idx & 3;
            cp16(base + PJ_WHI + (uint32_t)r * 80 + sg * 16,
                 d_W_hi + (size_t)(obase + r) * 256 + kc + sg * 8);
            cp16(base + PJ_WLO + (uint32_t)r * 80 + sg * 16,
                 d_W_lo + (size_t)(obase + r) * 256 + kc + sg * 8);
            int xr = idx >> 4, xs = idx & 15;
            cp16(base + PJ_XHI + (uint32_t)xr * 272 + xs * 16,
                 d_x_hi + (size_t)(b * C + kc + xr) * N + n0 + xs * 8);
            cp16(base + PJ_XLO + (uint32_t)xr * 272 + xs * 16,
                 d_x_lo + (size_t)(b * C + kc + xr) * N + n0 + xs * 8);
        }
    };

    load_chunk(0, 0);
    CP_COMMIT();
    for (int c = 0; c < 8; ++c) {
        if (c + 1 < 8) { load_chunk((c + 1) & 1, (c + 1) * 32); CP_COMMIT(); CP_WAIT(1); }
        else           { CP_WAIT(0); }
        __syncthreads();
        uint32_t base = sb + (uint32_t)(c & 1) * PJ_STAGE;
#pragma unroll
        for (int kk = 0; kk < 2; ++kk) {
            uint32_t aaddr = base + PJ_WHI + (uint32_t)(wid * 16 + (lane & 15)) * 80
                           + (uint32_t)(lane >> 4) * 16 + (uint32_t)kk * 32;
            uint32_t ah0, ah1, ah2, ah3, al0, al1, al2, al3;
            ldsm_x4(aaddr, ah0, ah1, ah2, ah3);
            ldsm_x4(aaddr + (PJ_WLO - PJ_WHI), al0, al1, al2, al3);
#pragma unroll
            for (int nf = 0; nf < 16; ++nf) {
                uint32_t baddr = base + PJ_XHI
                               + (uint32_t)(kk * 16 + ((lane >> 3) & 1) * 8 + (lane & 7)) * 272
                               + (uint32_t)(lane >> 4) * (PJ_XLO - PJ_XHI)
                               + (uint32_t)nf * 16;
                uint32_t bh0, bh1, bl0, bl1;
                ldsm_x4_t(baddr, bh0, bh1, bl0, bl1);
                mma_bf16(acc[nf], ah0, ah1, ah2, ah3, bh0, bh1);
                mma_bf16(acc[nf], ah0, ah1, ah2, ah3, bl0, bl1);
                mma_bf16(acc[nf], al0, al1, al2, al3, bh0, bh1);
            }
        }
        __syncthreads();
    }

    // bias
    const float* bias = (mt == 0) ? b_g : (mt == 1) ? b_t : b_p;
    const int r0 = wid * 16 + gid, r1 = r0 + 8;
    const float br0 = bias[r0], br1 = bias[r1];
#pragma unroll
    for (int nf = 0; nf < 16; ++nf) {
        acc[nf][0] += br0; acc[nf][1] += br0;
        acc[nf][2] += br1; acc[nf][3] += br1;
    }

    // epilogue: stage bf16 in smem (272B pitch), coalesced global stores; hi then lo
    if (mt == 0) {
        __nv_bfloat16* dsts[2] = { d_g_hi + (size_t)(b * CI) * N + n0,
                                   d_g_lo + (size_t)(b * CI) * N + n0 };
#pragma unroll
        for (int rnd = 0; rnd < 2; ++rnd) {
#pragma unroll
            for (int nf = 0; nf < 16; ++nf) {
                int ncol = 8 * nf + 2 * tig;
                uint16_t h0 = f2bf(acc[nf][0]), h1 = f2bf(acc[nf][1]);
                uint16_t h2 = f2bf(acc[nf][2]), h3 = f2bf(acc[nf][3]);
                uint32_t v0, v1;
                if (rnd == 0) { v0 = pack2(h0, h1); v1 = pack2(h2, h3); }
                else {
                    v0 = pack2(f2bf(acc[nf][0] - bf2f(h0)), f2bf(acc[nf][1] - bf2f(h1)));
                    v1 = pack2(f2bf(acc[nf][2] - bf2f(h2)), f2bf(acc[nf][3] - bf2f(h3)));
                }
                *(uint32_t*)(smc + (uint32_t)r0 * 272 + (uint32_t)ncol * 2) = v0;
                *(uint32_t*)(smc + (uint32_t)r1 * 272 + (uint32_t)ncol * 2) = v1;
            }
            __syncthreads();
            for (int idx = tid; idx < 2048; idx += 256) {
                int row = idx >> 4, c16 = idx & 15;
                *(uint4*)(dsts[rnd] + (size_t)row * N + c16 * 8) =
                    *(const uint4*)(smc + (uint32_t)row * 272 + (uint32_t)c16 * 16);
            }
            __syncthreads();
        }
    } else {
        __nv_bfloat16* dsts[2];
        dsts[0] = (mt == 1) ? d_thT_hi : d_phT_hi;
        dsts[1] = (mt == 1) ? d_thT_lo : d_phT_lo;
#pragma unroll
        for (int rnd = 0; rnd < 2; ++rnd) {
#pragma unroll
            for (int nf = 0; nf < 16; ++nf) {
                int nc = 8 * nf + 2 * tig;
                uint16_t h0 = f2bf(acc[nf][0]), h1 = f2bf(acc[nf][1]);
                uint16_t h2 = f2bf(acc[nf][2]), h3 = f2bf(acc[nf][3]);
                uint16_t v0, v1, v2, v3;
                if (rnd == 0) { v0 = h0; v1 = h1; v2 = h2; v3 = h3; }
                else {
                    v0 = f2bf(acc[nf][0] - bf2f(h0)); v1 = f2bf(acc[nf][1] - bf2f(h1));
                    v2 = f2bf(acc[nf][2] - bf2f(h2)); v3 = f2bf(acc[nf][3] - bf2f(h3));
                }
                *(__nv_bfloat16*)(smc + (uint32_t)(nc + 0) * 272 + (uint32_t)r0 * 2) = __ushort_as_bfloat16(v0);
                *(__nv_bfloat16*)(smc + (uint32_t)(nc + 1) * 272 + (uint32_t)r0 * 2) = __ushort_as_bfloat16(v1);
                *(__nv_bfloat16*)(smc + (uint32_t)(nc + 0) * 272 + (uint32_t)r1 * 2) = __ushort_as_bfloat16(v2);
                *(__nv_bfloat16*)(smc + (uint32_t)(nc + 1) * 272 + (uint32_t)r1 * 2) = __ushort_as_bfloat16(v3);
            }
            __syncthreads();
            for (int idx = tid; idx < 2048; idx += 256) {
                int row = idx >> 4, c16 = idx & 15;
                *(uint4*)(dsts[rnd] + (size_t)(b * N + n0 + row) * CI + c16 * 8) =
                    *(const uint4*)(smc + (uint32_t)row * 272 + (uint32_t)c16 * 16);
            }
            __syncthreads();
        }
    }
}

// ============================================================================
// K2: HMMA flash attention, cp.async 2-stage pipelined tiles.
// Block = 128 query rows; 8 warps x 16 rows. Loop m-tiles of 64.
// grid (32, 4), 256 threads, dyn smem 143360 B (2 stages x 71680).
// ============================================================================
#define PHI_PITCH 272
#define G_PITCH   144
#define OFF_PHI_HI 0u
#define OFF_PHI_LO 17408u
#define OFF_G_HI   34816u
#define OFF_G_LO   53248u
#define ATTN_STAGE 71680u
#define ATTN_SMEM  143360

__global__ void __launch_bounds__(256, 1) attn_kernel()
{
    extern __shared__ char smc[];
    const uint32_t sb = smem_u32(smc);
    const int b   = blockIdx.y;
    const int n0  = blockIdx.x * 128;
    const int tid = threadIdx.x;
    const int wid = tid >> 5, lane = tid & 31;
    const int gid = lane >> 2, tig = lane & 3;
    const int sel = lane >> 3, lr = lane & 7;

    auto stage_load = [&](int st, int it) {
        const int m0 = it * 64;
        uint32_t base = sb + (uint32_t)st * ATTN_STAGE;
        const __nv_bfloat16* ph = d_phT_hi + (size_t)(b * N + m0) * CI;
        const __nv_bfloat16* pl = d_phT_lo + (size_t)(b * N + m0) * CI;
        for (int idx = tid; idx < 64 * 16; idx += 256) {
            int r = idx >> 4, ch = idx & 15;
            uint32_t o = (uint32_t)r * PHI_PITCH + (uint32_t)ch * 16;
            cp16(base + OFF_PHI_HI + o, ph + (size_t)r * CI + ch * 8);
            cp16(base + OFF_PHI_LO + o, pl + (size_t)r * CI + ch * 8);
        }
        const __nv_bfloat16* gh = d_g_hi + (size_t)b * CI * N + m0;
        const __nv_bfloat16* gl = d_g_lo + (size_t)b * CI * N + m0;
        for (int idx = tid; idx < 128 * 8; idx += 256) {
            int r = idx >> 3, ch = idx & 7;
            uint32_t o = (uint32_t)r * G_PITCH + (uint32_t)ch * 16;
            cp16(base + OFF_G_HI + o, gh + (size_t)r * N + ch * 8);
            cp16(base + OFF_G_LO + o, gl + (size_t)r * N + ch * 8);
        }
    };

    stage_load(0, 0);
    CP_COMMIT();

    // ---- load theta A-fragments once (16 rows per warp), hi+lo ----
    uint32_t a_hi[8][4], a_lo[8][4];
    {
        const size_t rowbase = (size_t)(b * N + n0 + 16 * wid);
        const __nv_bfloat16* th = d_thT_hi + rowbase * CI;
        const __nv_bfloat16* tl = d_thT_lo + rowbase * CI;
        const int r0 = gid, r1 = gid + 8, c0 = 2 * tig;
#pragma unroll
        for (int k = 0; k < 8; k++) {
            a_hi[k][0] = *(const uint32_t*)(th + (size_t)r0 * CI + 16 * k + c0);
            a_hi[k][1] = *(const uint32_t*)(th + (size_t)r1 * CI + 16 * k + c0);
            a_hi[k][2] = *(const uint32_t*)(th + (size_t)r0 * CI + 16 * k + c0 + 8);
            a_hi[k][3] = *(const uint32_t*)(th + (size_t)r1 * CI + 16 * k + c0 + 8);
            a_lo[k][0] = *(const uint32_t*)(tl + (size_t)r0 * CI + 16 * k + c0);
            a_lo[k][1] = *(const uint32_t*)(tl + (size_t)r1 * CI + 16 * k + c0);
            a_lo[k][2] = *(const uint32_t*)(tl + (size_t)r0 * CI + 16 * k + c0 + 8);
            a_lo[k][3] = *(const uint32_t*)(tl + (size_t)r1 * CI + 16 * k + c0 + 8);
        }
    }

    float y[16][4];
#pragma unroll
    for (int t = 0; t < 16; t++)
#pragma unroll
        for (int e = 0; e < 4; e++) y[t][e] = 0.f;
    float l_lo = 0.f, l_hi = 0.f;

    for (int it = 0; it < 64; ++it) {
        if (it + 1 < 64) { stage_load((it + 1) & 1, it + 1); CP_COMMIT(); CP_WAIT(1); }
        else             { CP_WAIT(0); }
        __syncthreads();
        const uint32_t stb = sb + (uint32_t)(it & 1) * ATTN_STAGE;

        // ---- QK: S[16 x 64] ----
        float s[8][4];
#pragma unroll
        for (int j = 0; j < 8; j++)
#pragma unroll
            for (int e = 0; e < 4; e++) s[j][e] = 0.f;

#pragma unroll
        for (int j = 0; j < 8; j++) {
#pragma unroll
            for (int k = 0; k < 8; k++) {
                uint32_t addr = stb + ((sel >= 2) ? OFF_PHI_LO : OFF_PHI_HI)
                              + (uint32_t)(8 * j + lr) * PHI_PITCH
                              + (uint32_t)k * 32 + (uint32_t)(sel & 1) * 16;
                uint32_t bh0, bh1, bl0, bl1;
                ldsm_x4(addr, bh0, bh1, bl0, bl1);
                mma_bf16(s[j], a_hi[k][0], a_hi[k][1], a_hi[k][2], a_hi[k][3], bh0, bh1);
                mma_bf16(s[j], a_hi[k][0], a_hi[k][1], a_hi[k][2], a_hi[k][3], bl0, bl1);
                mma_bf16(s[j], a_lo[k][0], a_lo[k][1], a_lo[k][2], a_lo[k][3], bh0, bh1);
            }
        }

        // ---- exp + rowsum + pack P fragments (registers only) ----
        float rs0 = 0.f, rs1 = 0.f;
        uint32_t pa_hi[4][4], pa_lo[4][4];
#pragma unroll
        for (int j = 0; j < 8; j++) {
#pragma unroll
            for (int e = 0; e < 4; e++) s[j][e] = __expf(s[j][e]);
            rs0 += s[j][0] + s[j][1];
            rs1 += s[j][2] + s[j][3];
        }
#pragma unroll
        for (int k = 0; k < 4; k++) {
            const int j0 = 2 * k, j1 = 2 * k + 1;
            uint16_t h00 = f2bf(s[j0][0]), h01 = f2bf(s[j0][1]);
            uint16_t h02 = f2bf(s[j0][2]), h03 = f2bf(s[j0][3]);
            uint16_t h10 = f2bf(s[j1][0]), h11 = f2bf(s[j1][1]);
            uint16_t h12 = f2bf(s[j1][2]), h13 = f2bf(s[j1][3]);
            pa_hi[k][0] = pack2(h00, h01);
            pa_hi[k][1] = pack2(h02, h03);
            pa_hi[k][2] = pack2(h10, h11);
            pa_hi[k][3] = pack2(h12, h13);
            pa_lo[k][0] = pack2(f2bf(s[j0][0] - bf2f(h00)), f2bf(s[j0][1] - bf2f(h01)));
            pa_lo[k][1] = pack2(f2bf(s[j0][2] - bf2f(h02)), f2bf(s[j0][3] - bf2f(h03)));
            pa_lo[k][2] = pack2(f2bf(s[j1][0] - bf2f(h10)), f2bf(s[j1][1] - bf2f(h11)));
            pa_lo[k][3] = pack2(f2bf(s[j1][2] - bf2f(h12)), f2bf(s[j1][3] - bf2f(h13)));
        }
        rs0 += __shfl_xor_sync(0xffffffffu, rs0, 1);
        rs0 += __shfl_xor_sync(0xffffffffu, rs0, 2);
        rs1 += __shfl_xor_sync(0xffffffffu, rs1, 1);
        rs1 += __shfl_xor_sync(0xffffffffu, rs1, 2);
        l_lo += rs0;
        l_hi += rs1;

        // ---- PV: Y[16 x 128] += P * G^T ----
#pragma unroll
        for (int ct = 0; ct < 16; ct++) {
#pragma unroll
            for (int k = 0; k < 4; k++) {
                uint32_t addr = stb + ((sel >= 2) ? OFF_G_LO : OFF_G_HI)
                              + (uint32_t)(8 * ct + lr) * G_PITCH
                              + (uint32_t)k * 32 + (uint32_t)(sel & 1) * 16;
                uint32_t gh0, gh1, gl0, gl1;
                ldsm_x4(addr, gh0, gh1, gl0, gl1);
                mma_bf16(y[ct], pa_hi[k][0], pa_hi[k][1], pa_hi[k][2], pa_hi[k][3], gh0, gh1);
                mma_bf16(y[ct], pa_hi[k][0], pa_hi[k][1], pa_hi[k][2], pa_hi[k][3], gl0, gl1);
                mma_bf16(y[ct], pa_lo[k][0], pa_lo[k][1], pa_lo[k][2], pa_lo[k][3], gh0, gh1);
            }
        }
        __syncthreads();
    }

    // ---- normalize + transpose via smem -> coalesced d_y [b][c][n] ----
    float* ysm = (float*)smc;  // [128 c][pitch 132] floats
    const float inv0 = 1.f / l_lo, inv1 = 1.f / l_hi;
    const int nl0 = 16 * wid + gid, nl1 = nl0 + 8;
#pragma unroll
    for (int ct = 0; ct < 16; ct++) {
        int c = 8 * ct + 2 * tig;
        ysm[(c + 0) * 132 + nl0] = y[ct][0] * inv0;
        ysm[(c + 1) * 132 + nl0] = y[ct][1] * inv0;
        ysm[(c + 0) * 132 + nl1] = y[ct][2] * inv1;
        ysm[(c + 1) * 132 + nl1] = y[ct][3] * inv1;
    }
    __syncthreads();
    for (int idx = tid; idx < 128 * 128; idx += 256) {
        int c = idx >> 7, n = idx & 127;
        d_y[(size_t)(b * CI + c) * N + n0 + n] = ysm[c * 132 + n];
    }
}

// ============================================================================
// K3: W_y = w_out @ y + b_out, plus deterministic BN partial sums per block.
// grid (4, 32, 4), 256 threads.
// ============================================================================
__global__ void wy_kernel(const float* __restrict__ w_out, const float* __restrict__ b_out)
{
    __shared__ float Ws[32][65];
    __shared__ float Ys[32][128];
    const int b  = blockIdx.z;
    const int n0 = blockIdx.y * 128;
    const int o0 = blockIdx.x * 64;
    const int tid = threadIdx.x;
    const int tx = tid & 15, ty = tid >> 4;

    float acc[4][8];
#pragma unroll
    for (int i = 0; i < 4; i++)
#pragma unroll
        for (int j = 0; j < 8; j++) acc[i][j] = 0.f;

    for (int kc = 0; kc < CI; kc += 32) {
        for (int idx = tid; idx < 64 * 32; idx += 256) {
            int o = idx >> 5, k = idx & 31;
            Ws[k][o] = w_out[(o0 + o) * CI + kc + k];
        }
        for (int idx = tid; idx < 32 * 128; idx += 256) {
            int k = idx >> 7, n = idx & 127;
            Ys[k][n] = d_y[(size_t)(b * CI + kc + k) * N + n0 + n];
        }
        __syncthreads();
#pragma unroll 4
        for (int k = 0; k < 32; k++) {
            float a0 = Ws[k][ty * 4 + 0], a1 = Ws[k][ty * 4 + 1];
            float a2 = Ws[k][ty * 4 + 2], a3 = Ws[k][ty * 4 + 3];
            const float4 v0 = *(const float4*)&Ys[k][tx * 8];
            const float4 v1 = *(const float4*)&Ys[k][tx * 8 + 4];
            float bv[8] = {v0.x, v0.y, v0.z, v0.w, v1.x, v1.y, v1.z, v1.w};
#pragma unroll
            for (int j = 0; j < 8; j++) {
                acc[0][j] += a0 * bv[j];
                acc[1][j] += a1 * bv[j];
                acc[2][j] += a2 * bv[j];
                acc[3][j] += a3 * bv[j];
            }
        }
        __syncthreads();
    }

#pragma unroll
    for (int i = 0; i < 4; i++) {
        int oc = o0 + ty * 4 + i;
        float bb = b_out[oc];
        float s = 0.f, q = 0.f;
        float* p = d_wy + (size_t)(b * C + oc) * N + n0 + tx * 8;
#pragma unroll
        for (int j = 0; j < 8; j++) {
            float vv = acc[i][j] + bb;
            p[j] = vv;
            s += vv;
            q += vv * vv;
        }
#pragma unroll
        for (int off = 1; off < 16; off <<= 1) {
            s += __shfl_xor_sync(0xffffffffu, s, off);
            q += __shfl_xor_sync(0xffffffffu, q, off);
        }
        if (tx == 0) {
            int part = b * 32 + blockIdx.y;
            d_psum[oc * 128 + part] = s;
            d_psq[oc * 128 + part]  = q;
        }
    }
}

// ============================================================================
// K4: reduce BN partials -> per-channel scale/shift. grid C=256, 32 threads.
// ============================================================================
__global__ void bnstat_kernel(const float* __restrict__ gamma, const float* __restrict__ beta)
{
    int c = blockIdx.x, t = threadIdx.x;
    float s = 0.f, q = 0.f;
#pragma unroll
    for (int p = t; p < 128; p += 32) {
        s += d_psum[c * 128 + p];
        q += d_psq[c * 128 + p];
    }
#pragma unroll
    for (int off = 1; off < 32; off <<= 1) {
        s += __shfl_xor_sync(0xffffffffu, s, off);
        q += __shfl_xor_sync(0xffffffffu, q, off);
    }
    if (t == 0) {
        const float invn = 1.f / 16384.f;  // B*N
        float mean = s * invn;
        float var  = q * invn - mean * mean;
        float sc   = gamma[c] * rsqrtf(var + 1e-5f);
        d_bnA[c] = sc;
        d_bnB[c] = beta[c] - mean * sc;
    }
}

// ============================================================================
// K5: out = W_y * scale[c] + shift[c] + x
// ============================================================================
__global__ void bnadd_kernel(const float* __restrict__ x, float* __restrict__ out)
{
    int idx4 = blockIdx.x * blockDim.x + threadIdx.x;
    if (idx4 >= B * C * N / 4) return;
    int c = (idx4 >> 10) & (C - 1);
    float sc = d_bnA[c], bb = d_bnB[c];
    float4 w  = ((const float4*)d_wy)[idx4];
    float4 xv = ((const float4*)x)[idx4];
    float4 r;
    r.x = w.x * sc + bb + xv.x;
    r.y = w.y * sc + bb + xv.y;
    r.z = w.z * sc + bb + xv.z;
    r.w = w.w * sc + bb + xv.w;
    ((float4*)out)[idx4] = r;
}

// ============================================================================
extern "C" void kernel_launch(void* const* d_in, const int* in_sizes, int n_in,
                              void* d_out, int out_size)
{
    const float* x     = (const float*)d_in[0];
    const float* w_g   = (const float*)d_in[1];
    const float* b_g   = (const float*)d_in[2];
    const float* w_t   = (const float*)d_in[3];
    const float* b_t   = (const float*)d_in[4];
    const float* w_p   = (const float*)d_in[5];
    const float* b_p   = (const float*)d_in[6];
    const float* w_o   = (const float*)d_in[7];
    const float* b_o   = (const float*)d_in[8];
    const float* gamma = (const float*)d_in[9];
    const float* beta  = (const float*)d_in[10];
    float* out = (float*)d_out;

    cudaFuncSetAttribute(proj_kernel, cudaFuncAttributeMaxDynamicSharedMemorySize, PROJ_SMEM);
    cudaFuncSetAttribute(attn_kernel, cudaFuncAttributeMaxDynamicSharedMemorySize, ATTN_SMEM);

    splitw_kernel<<<384, 256>>>(w_g, w_t, w_p);
    splitx_kernel<<<4096, 256>>>(x);
    proj_kernel<<<dim3(3, 32, 4), 256, PROJ_SMEM>>>(b_g, b_t, b_p);
    attn_kernel<<<dim3(32, 4), 256, ATTN_SMEM>>>();
    wy_kernel<<<dim3(4, 32, 4), 256>>>(w_o, b_o);
    bnstat_kernel<<<256, 32>>>(gamma, beta);
    bnadd_kernel<<<4096, 256>>>(x, out);
}

// round 11
// speedup vs baseline: 3.8815x; 1.0070x over previous
#include <cuda_runtime.h>
#include <cuda_bf16.h>
#include <cstdint>

// NonlocalBlock: B=4, C=256, Ci=128, H=W=64 (N=4096)
// out = BN(w_out @ softmax(theta^T phi) @ g^T) + x
// HMMA (mma.sync bf16) everywhere heavy, bf16x2 hi/lo compensation (3 chains).
// cp.async 2-stage pipelines. Attn: theta staged in SMEM, k-outer QK loop
// to cut register pressure (R8 had regs=255 -> spills -> tensor pipe 60%).

namespace {
constexpr int B  = 4;
constexpr int C  = 256;
constexpr int CI = 128;
constexpr int N  = 4096;
}

// ---- scratch (static device globals; no runtime allocation allowed) ----
__device__ float d_y[B * CI * N];
__device__ float d_wy[B * C * N];
__device__ float d_psum[C * 128];
__device__ float d_psq[C * 128];
__device__ float d_bnA[C];
__device__ float d_bnB[C];
// bf16 hi/lo operands
__device__ alignas(16) __nv_bfloat16 d_thT_hi[B * N * CI];  // [b][n][ci]
__device__ alignas(16) __nv_bfloat16 d_thT_lo[B * N * CI];
__device__ alignas(16) __nv_bfloat16 d_phT_hi[B * N * CI];  // [b][m][ci]
__device__ alignas(16) __nv_bfloat16 d_phT_lo[B * N * CI];
__device__ alignas(16) __nv_bfloat16 d_g_hi[B * CI * N];    // [b][c][m]
__device__ alignas(16) __nv_bfloat16 d_g_lo[B * CI * N];
// split inputs for HMMA proj
__device__ alignas(16) __nv_bfloat16 d_W_hi[384 * 256];
__device__ alignas(16) __nv_bfloat16 d_W_lo[384 * 256];
__device__ alignas(16) __nv_bfloat16 d_x_hi[B * C * N];     // [b][c][n]
__device__ alignas(16) __nv_bfloat16 d_x_lo[B * C * N];

// ============================================================================
// helpers
// ============================================================================
__device__ __forceinline__ uint32_t smem_u32(const void* p) {
    uint32_t a;
    asm("{ .reg .u64 t; cvta.to.shared.u64 t, %1; cvt.u32.u64 %0, t; }" : "=r"(a) : "l"(p));
    return a;
}
__device__ __forceinline__ uint16_t f2bf(float v) {
    return __bfloat16_as_ushort(__float2bfloat16(v));
}
__device__ __forceinline__ float bf2f(uint16_t u) {
    return __bfloat162float(__ushort_as_bfloat16(u));
}
__device__ __forceinline__ uint32_t pack2(uint16_t lo, uint16_t hi) {
    return (uint32_t)lo | ((uint32_t)hi << 16);
}
__device__ __forceinline__ void mma_bf16(float* c,
                                         uint32_t a0, uint32_t a1, uint32_t a2, uint32_t a3,
                                         uint32_t b0, uint32_t b1) {
    asm volatile(
        "mma.sync.aligned.m16n8k16.row.col.f32.bf16.bf16.f32 "
        "{%0,%1,%2,%3}, {%4,%5,%6,%7}, {%8,%9}, {%0,%1,%2,%3};"
        : "+f"(c[0]), "+f"(c[1]), "+f"(c[2]), "+f"(c[3])
        : "r"(a0), "r"(a1), "r"(a2), "r"(a3), "r"(b0), "r"(b1));
}
__device__ __forceinline__ void ldsm_x4(uint32_t addr, uint32_t& r0, uint32_t& r1,
                                        uint32_t& r2, uint32_t& r3) {
    asm volatile("ldmatrix.sync.aligned.m8n8.x4.shared.b16 {%0,%1,%2,%3}, [%4];"
                 : "=r"(r0), "=r"(r1), "=r"(r2), "=r"(r3) : "r"(addr));
}
__device__ __forceinline__ void ldsm_x4_t(uint32_t addr, uint32_t& r0, uint32_t& r1,
                                          uint32_t& r2, uint32_t& r3) {
    asm volatile("ldmatrix.sync.aligned.m8n8.x4.trans.shared.b16 {%0,%1,%2,%3}, [%4];"
                 : "=r"(r0), "=r"(r1), "=r"(r2), "=r"(r3) : "r"(addr));
}
__device__ __forceinline__ void cp16(uint32_t saddr, const void* gaddr) {
    asm volatile("cp.async.cg.shared.global [%0], [%1], 16;" :: "r"(saddr), "l"(gaddr));
}
#define CP_COMMIT() asm volatile("cp.async.commit_group;" ::: "memory")
#define CP_WAIT(n)  asm volatile("cp.async.wait_group %0;" :: "n"(n) : "memory")

// ============================================================================
// K0a: split weights (w_g|w_t|w_p rows) -> d_W_hi/lo. grid 384 x 256.
// ============================================================================
__global__ void splitw_kernel(const float* __restrict__ w_g,
                              const float* __restrict__ w_t,
                              const float* __restrict__ w_p)
{
    int row = blockIdx.x, t = threadIdx.x;
    const float* src = (row < 128) ? w_g + (size_t)row * 256
                     : (row < 256) ? w_t + (size_t)(row - 128) * 256
                                   : w_p + (size_t)(row - 256) * 256;
    float v = src[t];
    uint16_t h = f2bf(v);
    d_W_hi[(size_t)row * 256 + t] = __ushort_as_bfloat16(h);
    d_W_lo[(size_t)row * 256 + t] = __ushort_as_bfloat16(f2bf(v - bf2f(h)));
}

// ============================================================================
// K0b: split x -> d_x_hi/lo. grid 4096 x 256, float4 per thread.
// ============================================================================
__global__ void splitx_kernel(const float* __restrict__ x)
{
    int idx4 = blockIdx.x * blockDim.x + threadIdx.x;  // < B*C*N/4
    float4 v = ((const float4*)x)[idx4];
    uint16_t h0 = f2bf(v.x), h1 = f2bf(v.y), h2 = f2bf(v.z), h3 = f2bf(v.w);
    *(uint2*)(d_x_hi + (size_t)idx4 * 4) = make_uint2(pack2(h0, h1), pack2(h2, h3));
    *(uint2*)(d_x_lo + (size_t)idx4 * 4) =
        make_uint2(pack2(f2bf(v.x - bf2f(h0)), f2bf(v.y - bf2f(h1))),
                   pack2(f2bf(v.z - bf2f(h2)), f2bf(v.w - bf2f(h3))));
}

// ============================================================================
// K1: HMMA projection GEMM. grid (3, 32, 4), 256 thr, cp.async 2-stage.
// ============================================================================
#define PJ_WHI   0u
#define PJ_WLO   10240u
#define PJ_XHI   20480u
#define PJ_XLO   29184u
#define PJ_STAGE 37888u
#define PROJ_SMEM 75776

__global__ void __launch_bounds__(256, 2) proj_kernel(const float* __restrict__ b_g,
                                                      const float* __restrict__ b_t,
                                                      const float* __restrict__ b_p)
{
    extern __shared__ char smc[];
    const uint32_t sb = smem_u32(smc);
    const int mt = blockIdx.x;
    const int n0 = blockIdx.y * 128;
    const int b  = blockIdx.z;
    const int tid = threadIdx.x, wid = tid >> 5, lane = tid & 31;
    const int gid = lane >> 2, tig = lane & 3;
    const int obase = mt * 128;

    float acc[16][4];
#pragma unroll
    for (int nf = 0; nf < 16; nf++)
#pragma unroll
        for (int e = 0; e < 4; e++) acc[nf][e] = 0.f;

    auto load_chunk = [&](int st, int kc) {
        uint32_t base = sb + (uint32_t)st * PJ_STAGE;
        for (int idx = tid; idx < 512; idx += 256) {
            int r = idx >> 2, sg = idx & 3;
            cp16(base + PJ_WHI + (uint32_t)r * 80 + sg * 16,
                 d_W_hi + (size_t)(obase + r) * 256 + kc + sg * 8);
            cp16(base + PJ_WLO + (uint32_t)r * 80 + sg * 16,
                 d_W_lo + (size_t)(obase + r) * 256 + kc + sg * 8);
            int xr = idx >> 4, xs = idx & 15;
            cp16(base + PJ_XHI + (uint32_t)xr * 272 + xs * 16,
                 d_x_hi + (size_t)(b * C + kc + xr) * N + n0 + xs * 8);
            cp16(base + PJ_XLO + (uint32_t)xr * 272 + xs * 16,
                 d_x_lo + (size_t)(b * C + kc + xr) * N + n0 + xs * 8);
        }
    };

    load_chunk(0, 0);
    CP_COMMIT();
    for (int c = 0; c < 8; ++c) {
        if (c + 1 < 8) { load_chunk((c + 1) & 1, (c + 1) * 32); CP_COMMIT(); CP_WAIT(1); }
        else           { CP_WAIT(0); }
        __syncthreads();
        uint32_t base = sb + (uint32_t)(c & 1) * PJ_STAGE;
#pragma unroll
        for (int kk = 0; kk < 2; ++kk) {
            uint32_t aaddr = base + PJ_WHI + (uint32_t)(wid * 16 + (lane & 15)) * 80
                           + (uint32_t)(lane >> 4) * 16 + (uint32_t)kk * 32;
            uint32_t ah0, ah1, ah2, ah3, al0, al1, al2, al3;
            ldsm_x4(aaddr, ah0, ah1, ah2, ah3);
            ldsm_x4(aaddr + (PJ_WLO - PJ_WHI), al0, al1, al2, al3);
#pragma unroll
            for (int nf = 0; nf < 16; ++nf) {
                uint32_t baddr = base + PJ_XHI
                               + (uint32_t)(kk * 16 + ((lane >> 3) & 1) * 8 + (lane & 7)) * 272
                               + (uint32_t)(lane >> 4) * (PJ_XLO - PJ_XHI)
                               + (uint32_t)nf * 16;
                uint32_t bh0, bh1, bl0, bl1;
                ldsm_x4_t(baddr, bh0, bh1, bl0, bl1);
                mma_bf16(acc[nf], ah0, ah1, ah2, ah3, bh0, bh1);
                mma_bf16(acc[nf], ah0, ah1, ah2, ah3, bl0, bl1);
                mma_bf16(acc[nf], al0, al1, al2, al3, bh0, bh1);
            }
        }
        __syncthreads();
    }

    const float* bias = (mt == 0) ? b_g : (mt == 1) ? b_t : b_p;
    const int r0 = wid * 16 + gid, r1 = r0 + 8;
    const float br0 = bias[r0], br1 = bias[r1];
#pragma unroll
    for (int nf = 0; nf < 16; ++nf) {
        acc[nf][0] += br0; acc[nf][1] += br0;
        acc[nf][2] += br1; acc[nf][3] += br1;
    }

    if (mt == 0) {
        __nv_bfloat16* dsts[2] = { d_g_hi + (size_t)(b * CI) * N + n0,
                                   d_g_lo + (size_t)(b * CI) * N + n0 };
#pragma unroll
        for (int rnd = 0; rnd < 2; ++rnd) {
#pragma unroll
            for (int nf = 0; nf < 16; ++nf) {
                int ncol = 8 * nf + 2 * tig;
                uint16_t h0 = f2bf(acc[nf][0]), h1 = f2bf(acc[nf][1]);
                uint16_t h2 = f2bf(acc[nf][2]), h3 = f2bf(acc[nf][3]);
                uint32_t v0, v1;
                if (rnd == 0) { v0 = pack2(h0, h1); v1 = pack2(h2, h3); }
                else {
                    v0 = pack2(f2bf(acc[nf][0] - bf2f(h0)), f2bf(acc[nf][1] - bf2f(h1)));
                    v1 = pack2(f2bf(acc[nf][2] - bf2f(h2)), f2bf(acc[nf][3] - bf2f(h3)));
                }
                *(uint32_t*)(smc + (uint32_t)r0 * 272 + (uint32_t)ncol * 2) = v0;
                *(uint32_t*)(smc + (uint32_t)r1 * 272 + (uint32_t)ncol * 2) = v1;
            }
            __syncthreads();
            for (int idx = tid; idx < 2048; idx += 256) {
                int row = idx >> 4, c16 = idx & 15;
                *(uint4*)(dsts[rnd] + (size_t)row * N + c16 * 8) =
                    *(const uint4*)(smc + (uint32_t)row * 272 + (uint32_t)c16 * 16);
            }
            __syncthreads();
        }
    } else {
        __nv_bfloat16* dsts[2];
        dsts[0] = (mt == 1) ? d_thT_hi : d_phT_hi;
        dsts[1] = (mt == 1) ? d_thT_lo : d_phT_lo;
#pragma unroll
        for (int rnd = 0; rnd < 2; ++rnd) {
#pragma unroll
            for (int nf = 0; nf < 16; ++nf) {
                int nc = 8 * nf + 2 * tig;
                uint16_t h0 = f2bf(acc[nf][0]), h1 = f2bf(acc[nf][1]);
                uint16_t h2 = f2bf(acc[nf][2]), h3 = f2bf(acc[nf][3]);
                uint16_t v0, v1, v2, v3;
                if (rnd == 0) { v0 = h0; v1 = h1; v2 = h2; v3 = h3; }
                else {
                    v0 = f2bf(acc[nf][0] - bf2f(h0)); v1 = f2bf(acc[nf][1] - bf2f(h1));
                    v2 = f2bf(acc[nf][2] - bf2f(h2)); v3 = f2bf(acc[nf][3] - bf2f(h3));
                }
                *(__nv_bfloat16*)(smc + (uint32_t)(nc + 0) * 272 + (uint32_t)r0 * 2) = __ushort_as_bfloat16(v0);
                *(__nv_bfloat16*)(smc + (uint32_t)(nc + 1) * 272 + (uint32_t)r0 * 2) = __ushort_as_bfloat16(v1);
                *(__nv_bfloat16*)(smc + (uint32_t)(nc + 0) * 272 + (uint32_t)r1 * 2) = __ushort_as_bfloat16(v2);
                *(__nv_bfloat16*)(smc + (uint32_t)(nc + 1) * 272 + (uint32_t)r1 * 2) = __ushort_as_bfloat16(v3);
            }
            __syncthreads();
            for (int idx = tid; idx < 2048; idx += 256) {
                int row = idx >> 4, c16 = idx & 15;
                *(uint4*)(dsts[rnd] + (size_t)(b * N + n0 + row) * CI + c16 * 8) =
                    *(const uint4*)(smc + (uint32_t)row * 272 + (uint32_t)c16 * 16);
            }
            __syncthreads();
        }
    }
}

// ============================================================================
// K2: HMMA flash attention. Theta tile staged in SMEM (not registers);
// QK is k-outer so only one A-fragment pair is live at a time.
// Block = 128 query rows; 8 warps x 16 rows. m-tiles of 64, cp.async 2-stage.
// grid (32, 4), 256 threads, dyn smem 212992 B.
// ============================================================================
#define TH_HI      0u
#define TH_LO      34816u
#define OFF_STAGES 69632u
#define PHI_PITCH  272
#define G_PITCH    144
#define ST_PHI_HI  0u
#define ST_PHI_LO  17408u
#define ST_G_HI    34816u
#define ST_G_LO    53248u
#define ATTN_STAGE 71680u
#define ATTN_SMEM  212992

__global__ void __launch_bounds__(256, 1) attn_kernel()
{
    extern __shared__ char smc[];
    const uint32_t sb = smem_u32(smc);
    const int b   = blockIdx.y;
    const int n0  = blockIdx.x * 128;
    const int tid = threadIdx.x;
    const int wid = tid >> 5, lane = tid & 31;
    const int gid = lane >> 2, tig = lane & 3;
    const int sel = lane >> 3, lr = lane & 7;

    // ---- theta tile -> smem (once, async) ----
    {
        const __nv_bfloat16* th = d_thT_hi + (size_t)(b * N + n0) * CI;
        const __nv_bfloat16* tl = d_thT_lo + (size_t)(b * N + n0) * CI;
        for (int idx = tid; idx < 128 * 16; idx += 256) {
            int r = idx >> 4, ch = idx & 15;
            uint32_t o = (uint32_t)r * PHI_PITCH + (uint32_t)ch * 16;
            cp16(sb + TH_HI + o, th + (size_t)r * CI + ch * 8);
            cp16(sb + TH_LO + o, tl + (size_t)r * CI + ch * 8);
        }
    }
    CP_COMMIT();

    auto stage_load = [&](int st, int it) {
        const int m0 = it * 64;
        uint32_t base = sb + OFF_STAGES + (uint32_t)st * ATTN_STAGE;
        const __nv_bfloat16* ph = d_phT_hi + (size_t)(b * N + m0) * CI;
        const __nv_bfloat16* pl = d_phT_lo + (size_t)(b * N + m0) * CI;
        for (int idx = tid; idx < 64 * 16; idx += 256) {
            int r = idx >> 4, ch = idx & 15;
            uint32_t o = (uint32_t)r * PHI_PITCH + (uint32_t)ch * 16;
            cp16(base + ST_PHI_HI + o, ph + (size_t)r * CI + ch * 8);
            cp16(base + ST_PHI_LO + o, pl + (size_t)r * CI + ch * 8);
        }
        const __nv_bfloat16* gh = d_g_hi + (size_t)b * CI * N + m0;
        const __nv_bfloat16* gl = d_g_lo + (size_t)b * CI * N + m0;
        for (int idx = tid; idx < 128 * 8; idx += 256) {
            int r = idx >> 3, ch = idx & 7;
            uint32_t o = (uint32_t)r * G_PITCH + (uint32_t)ch * 16;
            cp16(base + ST_G_HI + o, gh + (size_t)r * N + ch * 8);
            cp16(base + ST_G_LO + o, gl + (size_t)r * N + ch * 8);
        }
    };

    stage_load(0, 0);
    CP_COMMIT();

    float y[16][4];
#pragma unroll
    for (int t = 0; t < 16; t++)
#pragma unroll
        for (int e = 0; e < 4; e++) y[t][e] = 0.f;
    float l_lo = 0.f, l_hi = 0.f;

    const uint32_t a_base = sb + (uint32_t)(wid * 16 + (lane & 15)) * PHI_PITCH
                          + (uint32_t)(lane >> 4) * 16;

    for (int it = 0; it < 64; ++it) {
        if (it + 1 < 64) { stage_load((it + 1) & 1, it + 1); CP_COMMIT(); CP_WAIT(1); }
        else             { CP_WAIT(0); }
        __syncthreads();
        const uint32_t stb = sb + OFF_STAGES + (uint32_t)(it & 1) * ATTN_STAGE;

        // ---- QK: S[16 x 64], k-outer so A-fragments streamed from smem ----
        float s[8][4];
#pragma unroll
        for (int j = 0; j < 8; j++)
#pragma unroll
            for (int e = 0; e < 4; e++) s[j][e] = 0.f;

#pragma unroll
        for (int k = 0; k < 8; k++) {
            uint32_t aaddr = a_base + (uint32_t)k * 32;
            uint32_t ah0, ah1, ah2, ah3, al0, al1, al2, al3;
            ldsm_x4(aaddr + TH_HI, ah0, ah1, ah2, ah3);
            ldsm_x4(aaddr + TH_LO, al0, al1, al2, al3);
#pragma unroll
            for (int j = 0; j < 8; j++) {
                uint32_t addr = stb + ((sel >= 2) ? ST_PHI_LO : ST_PHI_HI)
                              + (uint32_t)(8 * j + lr) * PHI_PITCH
                              + (uint32_t)k * 32 + (uint32_t)(sel & 1) * 16;
                uint32_t bh0, bh1, bl0, bl1;
                ldsm_x4(addr, bh0, bh1, bl0, bl1);
                mma_bf16(s[j], ah0, ah1, ah2, ah3, bh0, bh1);
                mma_bf16(s[j], ah0, ah1, ah2, ah3, bl0, bl1);
                mma_bf16(s[j], al0, al1, al2, al3, bh0, bh1);
            }
        }

        // ---- exp + rowsum + pack P fragments (registers only) ----
        float rs0 = 0.f, rs1 = 0.f;
        uint32_t pa_hi[4][4], pa_lo[4][4];
#pragma unroll
        for (int j = 0; j < 8; j++) {
#pragma unroll
            for (int e = 0; e < 4; e++) s[j][e] = __expf(s[j][e]);
            rs0 += s[j][0] + s[j][1];
            rs1 += s[j][2] + s[j][3];
        }
#pragma unroll
        for (int k = 0; k < 4; k++) {
            const int j0 = 2 * k, j1 = 2 * k + 1;
            uint16_t h00 = f2bf(s[j0][0]), h01 = f2bf(s[j0][1]);
            uint16_t h02 = f2bf(s[j0][2]), h03 = f2bf(s[j0][3]);
            uint16_t h10 = f2bf(s[j1][0]), h11 = f2bf(s[j1][1]);
            uint16_t h12 = f2bf(s[j1][2]), h13 = f2bf(s[j1][3]);
            pa_hi[k][0] = pack2(h00, h01);
            pa_hi[k][1] = pack2(h02, h03);
            pa_hi[k][2] = pack2(h10, h11);
            pa_hi[k][3] = pack2(h12, h13);
            pa_lo[k][0] = pack2(f2bf(s[j0][0] - bf2f(h00)), f2bf(s[j0][1] - bf2f(h01)));
            pa_lo[k][1] = pack2(f2bf(s[j0][2] - bf2f(h02)), f2bf(s[j0][3] - bf2f(h03)));
            pa_lo[k][2] = pack2(f2bf(s[j1][0] - bf2f(h10)), f2bf(s[j1][1] - bf2f(h11)));
            pa_lo[k][3] = pack2(f2bf(s[j1][2] - bf2f(h12)), f2bf(s[j1][3] - bf2f(h13)));
        }
        rs0 += __shfl_xor_sync(0xffffffffu, rs0, 1);
        rs0 += __shfl_xor_sync(0xffffffffu, rs0, 2);
        rs1 += __shfl_xor_sync(0xffffffffu, rs1, 1);
        rs1 += __shfl_xor_sync(0xffffffffu, rs1, 2);
        l_lo += rs0;
        l_hi += rs1;

        // ---- PV: Y[16 x 128] += P * G^T ----
#pragma unroll
        for (int ct = 0; ct < 16; ct++) {
#pragma unroll
            for (int k = 0; k < 4; k++) {
                uint32_t addr = stb + ((sel >= 2) ? ST_G_LO : ST_G_HI)
                              + (uint32_t)(8 * ct + lr) * G_PITCH
                              + (uint32_t)k * 32 + (uint32_t)(sel & 1) * 16;
                uint32_t gh0, gh1, gl0, gl1;
                ldsm_x4(addr, gh0, gh1, gl0, gl1);
                mma_bf16(y[ct], pa_hi[k][0], pa_hi[k][1], pa_hi[k][2], pa_hi[k][3], gh0, gh1);
                mma_bf16(y[ct], pa_hi[k][0], pa_hi[k][1], pa_hi[k][2], pa_hi[k][3], gl0, gl1);
                mma_bf16(y[ct], pa_lo[k][0], pa_lo[k][1], pa_lo[k][2], pa_lo[k][3], gh0, gh1);
            }
        }
        __syncthreads();
    }

    // ---- normalize + transpose via smem -> coalesced d_y [b][c][n] ----
    float* ysm = (float*)smc;  // [128 c][pitch 132] floats (overwrites theta)
    const float inv0 = 1.f / l_lo, inv1 = 1.f / l_hi;
    const int nl0 = 16 * wid + gid, nl1 = nl0 + 8;
#pragma unroll
    for (int ct = 0; ct < 16; ct++) {
        int c = 8 * ct + 2 * tig;
        ysm[(c + 0) * 132 + nl0] = y[ct][0] * inv0;
        ysm[(c + 1) * 132 + nl0] = y[ct][1] * inv0;
        ysm[(c + 0) * 132 + nl1] = y[ct][2] * inv1;
        ysm[(c + 1) * 132 + nl1] = y[ct][3] * inv1;
    }
    __syncthreads();
    for (int idx = tid; idx < 128 * 128; idx += 256) {
        int c = idx >> 7, n = idx & 127;
        d_y[(size_t)(b * CI + c) * N + n0 + n] = ysm[c * 132 + n];
    }
}

// ============================================================================
// K3: W_y = w_out @ y + b_out, plus deterministic BN partial sums per block.
// grid (4, 32, 4), 256 threads.
// ============================================================================
__global__ void wy_kernel(const float* __restrict__ w_out, const float* __restrict__ b_out)
{
    __shared__ float Ws[32][65];
    __shared__ float Ys[32][128];
    const int b  = blockIdx.z;
    const int n0 = blockIdx.y * 128;
    const int o0 = blockIdx.x * 64;
    const int tid = threadIdx.x;
    const int tx = tid & 15, ty = tid >> 4;

    float acc[4][8];
#pragma unroll
    for (int i = 0; i < 4; i++)
#pragma unroll
        for (int j = 0; j < 8; j++) acc[i][j] = 0.f;

    for (int kc = 0; kc < CI; kc += 32) {
        for (int idx = tid; idx < 64 * 32; idx += 256) {
            int o = idx >> 5, k = idx & 31;
            Ws[k][o] = w_out[(o0 + o) * CI + kc + k];
        }
        for (int idx = tid; idx < 32 * 128; idx += 256) {
            int k = idx >> 7, n = idx & 127;
            Ys[k][n] = d_y[(size_t)(b * CI + kc + k) * N + n0 + n];
        }
        __syncthreads();
#pragma unroll 4
        for (int k = 0; k < 32; k++) {
            float a0 = Ws[k][ty * 4 + 0], a1 = Ws[k][ty * 4 + 1];
            float a2 = Ws[k][ty * 4 + 2], a3 = Ws[k][ty * 4 + 3];
            const float4 v0 = *(const float4*)&Ys[k][tx * 8];
            const float4 v1 = *(const float4*)&Ys[k][tx * 8 + 4];
            float bv[8] = {v0.x, v0.y, v0.z, v0.w, v1.x, v1.y, v1.z, v1.w};
#pragma unroll
            for (int j = 0; j < 8; j++) {
                acc[0][j] += a0 * bv[j];
                acc[1][j] += a1 * bv[j];
                acc[2][j] += a2 * bv[j];
                acc[3][j] += a3 * bv[j];
            }
        }
        __syncthreads();
    }

#pragma unroll
    for (int i = 0; i < 4; i++) {
        int oc = o0 + ty * 4 + i;
        float bb = b_out[oc];
        float s = 0.f, q = 0.f;
        float* p = d_wy + (size_t)(b * C + oc) * N + n0 + tx * 8;
#pragma unroll
        for (int j = 0; j < 8; j++) {
            float vv = acc[i][j] + bb;
            p[j] = vv;
            s += vv;
            q += vv * vv;
        }
#pragma unroll
        for (int off = 1; off < 16; off <<= 1) {
            s += __shfl_xor_sync(0xffffffffu, s, off);
            q += __shfl_xor_sync(0xffffffffu, q, off);
        }
        if (tx == 0) {
            int part = b * 32 + blockIdx.y;
            d_psum[oc * 128 + part] = s;
            d_psq[oc * 128 + part]  = q;
        }
    }
}

// ============================================================================
// K4: reduce BN partials -> per-channel scale/shift. grid C=256, 32 threads.
// ============================================================================
__global__ void bnstat_kernel(const float* __restrict__ gamma, const float* __restrict__ beta)
{
    int c = blockIdx.x, t = threadIdx.x;
    float s = 0.f, q = 0.f;
#pragma unroll
    for (int p = t; p < 128; p += 32) {
        s += d_psum[c * 128 + p];
        q += d_psq[c * 128 + p];
    }
#pragma unroll
    for (int off = 1; off < 32; off <<= 1) {
        s += __shfl_xor_sync(0xffffffffu, s, off);
        q += __shfl_xor_sync(0xffffffffu, q, off);
    }
    if (t == 0) {
        const float invn = 1.f / 16384.f;  // B*N
        float mean = s * invn;
        float var  = q * invn - mean * mean;
        float sc   = gamma[c] * rsqrtf(var + 1e-5f);
        d_bnA[c] = sc;
        d_bnB[c] = beta[c] - mean * sc;
    }
}

// ============================================================================
// K5: out = W_y * scale[c] + shift[c] + x
// ============================================================================
__global__ void bnadd_kernel(const float* __restrict__ x, float* __restrict__ out)
{
    int idx4 = blockIdx.x * blockDim.x + threadIdx.x;
    if (idx4 >= B * C * N / 4) return;
    int c = (idx4 >> 10) & (C - 1);
    float sc = d_bnA[c], bb = d_bnB[c];
    float4 w  = ((const float4*)d_wy)[idx4];
    float4 xv = ((const float4*)x)[idx4];
    float4 r;
    r.x = w.x * sc + bb + xv.x;
    r.y = w.y * sc + bb + xv.y;
    r.z = w.z * sc + bb + xv.z;
    r.w = w.w * sc + bb + xv.w;
    ((float4*)out)[idx4] = r;
}

// ============================================================================
extern "C" void kernel_launch(void* const* d_in, const int* in_sizes, int n_in,
                              void* d_out, int out_size)
{
    const float* x     = (const float*)d_in[0];
    const float* w_g   = (const float*)d_in[1];
    const float* b_g   = (const float*)d_in[2];
    const float* w_t   = (const float*)d_in[3];
    const float* b_t   = (const float*)d_in[4];
    const float* w_p   = (const float*)d_in[5];
    const float* b_p   = (const float*)d_in[6];
    const float* w_o   = (const float*)d_in[7];
    const float* b_o   = (const float*)d_in[8];
    const float* gamma = (const float*)d_in[9];
    const float* beta  = (const float*)d_in[10];
    float* out = (float*)d_out;

    cudaFuncSetAttribute(proj_kernel, cudaFuncAttributeMaxDynamicSharedMemorySize, PROJ_SMEM);
    cudaFuncSetAttribute(attn_kernel, cudaFuncAttributeMaxDynamicSharedMemorySize, ATTN_SMEM);

    splitw_kernel<<<384, 256>>>(w_g, w_t, w_p);
    splitx_kernel<<<4096, 256>>>(x);
    proj_kernel<<<dim3(3, 32, 4), 256, PROJ_SMEM>>>(b_g, b_t, b_p);
    attn_kernel<<<dim3(32, 4), 256, ATTN_SMEM>>>();
    wy_kernel<<<dim3(4, 32, 4), 256>>>(w_o, b_o);
    bnstat_kernel<<<256, 32>>>(gamma, beta);
    bnadd_kernel<<<4096, 256>>>(x, out);
}